// round 11
// baseline (speedup 1.0000x reference)
#include <cuda_runtime.h>
#include <math.h>

#define BB 4
#define TT 16
#define HH 64
#define WW 64
#define CIN 32
#define COUT 64
#define GG (4*COUT)   // 256 gate channels

typedef unsigned long long u64;

// Scratch: gx for all (b,t) pixels: (B*T*H*W, 256) floats = 268MB
__device__ float g_gx[(size_t)BB*TT*HH*WW*GG];
// Duplicated ping-pong hidden state: each channel stored as {h,h} pair
__device__ float g_h0d[(size_t)BB*HH*WW*COUT*2];
__device__ float g_h1d[(size_t)BB*HH*WW*COUT*2];
// Cell state
__device__ float g_c [(size_t)BB*HH*WW*COUT];
// Split transposed weights: [k][ci][lane(32)][4 floats]
// g01: {g0c0,g0c1,g1c0,g1c1}   g23: {g2c0,g2c1,g3c0,g3c1}   (c0=2*lane)
__device__ float g_rw01[9*COUT*32*4];
__device__ float g_rw23[9*COUT*32*4];
__device__ float g_wk01[9*CIN*32*4];
__device__ float g_wk23[9*CIN*32*4];

__device__ __forceinline__ float hsig(float z) {
    return fminf(fmaxf(0.2f*z + 0.5f, 0.0f), 1.0f);
}

__device__ __forceinline__ void fma_x2(u64& acc, u64 s, u64 w) {
    asm("fma.rn.f32x2 %0, %1, %2, %3;" : "=l"(acc) : "l"(s), "l"(w), "l"(acc));
}
__device__ __forceinline__ u64 pack2(float s) {
    u64 r;
    asm("mov.b64 %0, {%1, %1};" : "=l"(r) : "f"(s));
    return r;
}
__device__ __forceinline__ float2 unpack2(u64 v) {
    float2 f;
    asm("mov.b64 {%0, %1}, %2;" : "=f"(f.x), "=f"(f.y) : "l"(v));
    return f;
}

// ---------------------------------------------------------------------------
// Weight transpose prep.
// ---------------------------------------------------------------------------
__global__ __launch_bounds__(128)
void prep_weights(const float* __restrict__ wk, const float* __restrict__ rw)
{
    const int i = blockIdx.x * 128 + threadIdx.x;
    if (i < 9*COUT*32) {
        const int j  = i & 31;
        const int ci = (i >> 5) & 63;
        const int k  = i >> 11;
        const float* s = rw + ((size_t)(k*COUT + ci))*GG + 2*j;
        ((float4*)g_rw01)[i] = make_float4(s[0],   s[1],   s[64],  s[65]);
        ((float4*)g_rw23)[i] = make_float4(s[128], s[129], s[192], s[193]);
    }
    const int m = i - 9*COUT*32;
    if (m >= 0 && m < 9*CIN*32) {
        const int j  = m & 31;
        const int ci = (m >> 5) & 31;
        const int k  = m >> 10;
        const float* s = wk + ((size_t)(k*CIN + ci))*GG + 2*j;
        ((float4*)g_wk01)[m] = make_float4(s[0],   s[1],   s[64],  s[65]);
        ((float4*)g_wk23)[m] = make_float4(s[128], s[129], s[192], s[193]);
    }
}

// Chunked smem weight tile: [9 taps][4 ci][32 lanes] float4, for each of 2 arrays.
#define CHUNK 4
#define TILE4 (9*CHUNK*32)    // 1152 float4 per array

// ---------------------------------------------------------------------------
// Phase 1: input-to-gate conv (round-9 verified version).
// Thread: 8 pixels x (2 channels x 4 gates). Block 128 thr, grid 8192.
// ---------------------------------------------------------------------------
__global__ __launch_bounds__(128, 4)
void input_conv_kernel(const float* __restrict__ x,
                       const float* __restrict__ bias)
{
    __shared__ float4 s01[TILE4];
    __shared__ float4 s23[TILE4];

    const int tx   = threadIdx.x;
    const int lane = tx & 31;
    const int co0  = lane * 2;
    const int pg   = tx >> 5;
    const int bid  = blockIdx.x;
    const int bt   = bid >> 7;
    const int r    = bid & 127;
    const int py   = r >> 1;
    const int px0  = (r & 1) * 32 + pg * 8;
    const bool okL = (px0 > 0);
    const bool okR = (px0 < WW - 8);

    u64 acc[4][8];
    #pragma unroll
    for (int g = 0; g < 4; g++) {
        u64 bv = *(const u64*)(bias + g*COUT + co0);
        #pragma unroll
        for (int p = 0; p < 8; p++) acc[g][p] = bv;
    }

    const int iy0 = py - 1;
    const float* __restrict__ xbase = x + ((size_t)(bt*HH))*WW*CIN;

    #pragma unroll 1
    for (int cc = 0; cc < CIN; cc += CHUNK) {
        __syncthreads();
        #pragma unroll
        for (int i = tx; i < TILE4; i += 128) {
            const int tap  = i >> 7;
            const int rest = i & 127;
            const size_t src = (size_t)(tap*CIN + cc)*32 + rest;
            s01[i] = ((const float4*)g_wk01)[src];
            s23[i] = ((const float4*)g_wk23)[src];
        }
        __syncthreads();

        #pragma unroll
        for (int ky = 0; ky < 3; ky++) {
            const int iy = iy0 + ky;
            if ((unsigned)iy >= HH) continue;
            const float* __restrict__ xrow = xbase + ((size_t)iy*WW)*CIN;
            #pragma unroll
            for (int c4 = 0; c4 < CHUNK; c4++) {
                const int ci = cc + c4;
                u64 hv2[10];
                hv2[0] = okL ? pack2(xrow[(size_t)(px0-1)*CIN + ci]) : 0ULL;
                #pragma unroll
                for (int j = 1; j < 9; j++)
                    hv2[j] = pack2(xrow[(size_t)(px0-1+j)*CIN + ci]);
                hv2[9] = okR ? pack2(xrow[(size_t)(px0+8)*CIN + ci]) : 0ULL;
                #pragma unroll
                for (int kx = 0; kx < 3; kx++) {
                    const int sidx = ((ky*3+kx)*CHUNK + c4)*32 + lane;
                    const ulonglong2 wA = *reinterpret_cast<const ulonglong2*>(&s01[sidx]);
                    const ulonglong2 wB = *reinterpret_cast<const ulonglong2*>(&s23[sidx]);
                    #pragma unroll
                    for (int p = 0; p < 8; p++) {
                        const u64 s2 = hv2[p + kx];
                        fma_x2(acc[0][p], s2, wA.x);
                        fma_x2(acc[1][p], s2, wA.y);
                        fma_x2(acc[2][p], s2, wB.x);
                        fma_x2(acc[3][p], s2, wB.y);
                    }
                }
            }
        }
    }

    const size_t rowbase = ((size_t)bt*HH + py)*WW;
    #pragma unroll
    for (int p = 0; p < 8; p++) {
        float* __restrict__ o = g_gx + (rowbase + px0 + p)*GG + co0;
        *(u64*)(o + 0*COUT) = acc[0][p];
        *(u64*)(o + 1*COUT) = acc[1][p];
        *(u64*)(o + 2*COUT) = acc[2][p];
        *(u64*)(o + 3*COUT) = acc[3][p];
    }
}

// ---------------------------------------------------------------------------
// Phase 2: one recurrent step. 4 px/thread + paired-ci h loads + smem weights.
// Thread: 4 px x (2 ch x 4 gates) = 16 packed accs; hv = 6 ulonglong2.
// Block: 128 thr = 4 warps x 32 lanes = 16 px. Grid: B*H*4 = 1024.
// ---------------------------------------------------------------------------
template<bool FIRST>
__global__ __launch_bounds__(128, 4)
void step_kernel(float* __restrict__ y,
                 const int t,
                 const float* __restrict__ gamma,
                 const float* __restrict__ beta,
                 const float* __restrict__ mmean,
                 const float* __restrict__ mvar)
{
    __shared__ float4 s01[TILE4];
    __shared__ float4 s23[TILE4];

    const float* __restrict__ hprevd = (t & 1) ? g_h0d : g_h1d;
    float*       __restrict__ hnewd  = (t & 1) ? g_h1d : g_h0d;

    const int tx   = threadIdx.x;
    const int lane = tx & 31;
    const int co0  = lane * 2;
    const int pg   = tx >> 5;
    const int bid  = blockIdx.x;
    const int b    = bid >> 8;
    const int r    = bid & 255;
    const int py   = r >> 2;
    const int px0  = (r & 3) * 16 + pg * 4;
    const bool okL = (px0 > 0);
    const bool okR = (px0 < WW - 4);

    u64 acc[4][4];
    const size_t gxrow = ((size_t)(b*TT + t)*HH + py)*WW;
    #pragma unroll
    for (int p = 0; p < 4; p++) {
        const float* __restrict__ gp = g_gx + (gxrow + px0 + p)*GG + co0;
        acc[0][p] = *(const u64*)(gp + 0*COUT);
        acc[1][p] = *(const u64*)(gp + 1*COUT);
        acc[2][p] = *(const u64*)(gp + 2*COUT);
        acc[3][p] = *(const u64*)(gp + 3*COUT);
    }

    if (!FIRST) {
        const int iy0 = py - 1;
        const float* __restrict__ hbase = hprevd + ((size_t)(b*HH))*WW*(COUT*2);

        #pragma unroll 1
        for (int cc = 0; cc < COUT; cc += CHUNK) {
            __syncthreads();
            #pragma unroll
            for (int i = tx; i < TILE4; i += 128) {
                const int tap  = i >> 7;
                const int rest = i & 127;
                const size_t src = (size_t)(tap*COUT + cc)*32 + rest;
                s01[i] = ((const float4*)g_rw01)[src];
                s23[i] = ((const float4*)g_rw23)[src];
            }
            __syncthreads();

            #pragma unroll
            for (int ky = 0; ky < 3; ky++) {
                const int iy = iy0 + ky;
                if ((unsigned)iy >= HH) continue;
                const float* __restrict__ hrow = hbase + ((size_t)iy*WW)*(COUT*2);
                #pragma unroll
                for (int qq = 0; qq < CHUNK/2; qq++) {
                    const int fq = (cc >> 1) + qq;   // float4 slot within pixel
                    ulonglong2 hv[6];
                    hv[0] = okL ? *(const ulonglong2*)(hrow + (size_t)(px0-1)*(COUT*2) + fq*4)
                                : make_ulonglong2(0ULL, 0ULL);
                    #pragma unroll
                    for (int j = 1; j < 5; j++)
                        hv[j] = *(const ulonglong2*)(hrow + (size_t)(px0-1+j)*(COUT*2) + fq*4);
                    hv[5] = okR ? *(const ulonglong2*)(hrow + (size_t)(px0+4)*(COUT*2) + fq*4)
                                : make_ulonglong2(0ULL, 0ULL);
                    #pragma unroll
                    for (int kx = 0; kx < 3; kx++) {
                        const int s0 = ((ky*3+kx)*CHUNK + 2*qq)*32 + lane;
                        const ulonglong2 wA0 = *reinterpret_cast<const ulonglong2*>(&s01[s0]);
                        const ulonglong2 wB0 = *reinterpret_cast<const ulonglong2*>(&s23[s0]);
                        const ulonglong2 wA1 = *reinterpret_cast<const ulonglong2*>(&s01[s0+32]);
                        const ulonglong2 wB1 = *reinterpret_cast<const ulonglong2*>(&s23[s0+32]);
                        #pragma unroll
                        for (int p = 0; p < 4; p++) {
                            const u64 se = hv[p + kx].x;   // even ci
                            const u64 so = hv[p + kx].y;   // odd ci
                            fma_x2(acc[0][p], se, wA0.x);
                            fma_x2(acc[1][p], se, wA0.y);
                            fma_x2(acc[2][p], se, wB0.x);
                            fma_x2(acc[3][p], se, wB0.y);
                            fma_x2(acc[0][p], so, wA1.x);
                            fma_x2(acc[1][p], so, wA1.y);
                            fma_x2(acc[2][p], so, wB1.x);
                            fma_x2(acc[3][p], so, wB1.y);
                        }
                    }
                }
            }
        }
    }

    // BN constants for this thread's 2 channels
    float2 gm  = *(const float2*)(gamma + co0);
    float2 bt2 = *(const float2*)(beta  + co0);
    float2 mm  = *(const float2*)(mmean + co0);
    float2 mv  = *(const float2*)(mvar  + co0);
    float2 inv, add;
    inv.x = gm.x * rsqrtf(mv.x + 1e-3f); add.x = bt2.x - mm.x*inv.x;
    inv.y = gm.y * rsqrtf(mv.y + 1e-3f); add.y = bt2.y - mm.y*inv.y;

    const size_t pixrow = ((size_t)b*HH + py)*WW;
    #pragma unroll
    for (int p = 0; p < 4; p++) {
        const size_t pix = pixrow + px0 + p;

        float2 gi = unpack2(acc[0][p]);
        float2 gf = unpack2(acc[1][p]);
        float2 gg = unpack2(acc[2][p]);
        float2 go = unpack2(acc[3][p]);

        float2 i2, f2, o2;
        i2.x = hsig(gi.x); i2.y = hsig(gi.y);
        f2.x = hsig(gf.x); f2.y = hsig(gf.y);
        o2.x = hsig(go.x); o2.y = hsig(go.y);

        float* __restrict__ cp = g_c + pix*COUT + co0;
        float2 cold = FIRST ? make_float2(0.f,0.f) : *(const float2*)cp;

        float2 cn;
        cn.x = f2.x*cold.x + i2.x*tanhf(gg.x);
        cn.y = f2.y*cold.y + i2.y*tanhf(gg.y);
        *(float2*)cp = cn;

        float2 h2;
        h2.x = o2.x * tanhf(cn.x);
        h2.y = o2.y * tanhf(cn.y);
        *(float4*)(hnewd + pix*(COUT*2) + co0*2) = make_float4(h2.x, h2.x, h2.y, h2.y);

        float2 yv;
        yv.x = h2.x*inv.x + add.x;
        yv.y = h2.y*inv.y + add.y;
        float* __restrict__ yp = y + (gxrow + px0 + p)*COUT + co0;
        *(float2*)yp = yv;
    }
}

extern "C" void kernel_launch(void* const* d_in, const int* in_sizes, int n_in,
                              void* d_out, int out_size)
{
    const float* x      = (const float*)d_in[0];
    const float* wk     = (const float*)d_in[1];
    const float* rw     = (const float*)d_in[2];
    const float* bias   = (const float*)d_in[3];
    const float* gamma  = (const float*)d_in[4];
    const float* beta   = (const float*)d_in[5];
    const float* mmean  = (const float*)d_in[6];
    const float* mvar   = (const float*)d_in[7];
    float* y = (float*)d_out;

    // Prep: transpose/split weights (one-time per launch).
    const int n_prep = 9*COUT*32 + 9*CIN*32;
    prep_weights<<<(n_prep + 127)/128, 128>>>(wk, rw);

    // Phase 1: all input convs. 8192 blocks x 128 threads (32 px each).
    input_conv_kernel<<<BB*TT*HH*2, 128>>>(x, bias);

    // Phase 2: 16 sequential recurrent steps. 1024 blocks x 128 threads (16 px).
    const int nblk = BB*HH*4;
    step_kernel<true><<<nblk, 128>>>(y, 0, gamma, beta, mmean, mvar);
    for (int t = 1; t < TT; t++) {
        step_kernel<false><<<nblk, 128>>>(y, t, gamma, beta, mmean, mvar);
    }
}

// round 12
// speedup vs baseline: 1.3273x; 1.3273x over previous
#include <cuda_runtime.h>
#include <math.h>

#define BB 4
#define TT 16
#define HH 64
#define WW 64
#define CIN 32
#define COUT 64
#define GG (4*COUT)   // 256 gate channels

typedef unsigned long long u64;

// Scratch: gx for all (b,t) pixels: (B*T*H*W, 256) floats = 268MB
__device__ float g_gx[(size_t)BB*TT*HH*WW*GG];
// Duplicated ping-pong hidden state: each channel stored as {h,h} pair
__device__ float g_h0d[(size_t)BB*HH*WW*COUT*2];
__device__ float g_h1d[(size_t)BB*HH*WW*COUT*2];
// Cell state
__device__ float g_c [(size_t)BB*HH*WW*COUT];
// Split transposed weights: [k][ci][lane(32)][4 floats]
// g01: {g0c0,g0c1,g1c0,g1c1}   g23: {g2c0,g2c1,g3c0,g3c1}   (c0=2*lane)
__device__ float g_rw01[9*COUT*32*4];
__device__ float g_rw23[9*COUT*32*4];
__device__ float g_wk01[9*CIN*32*4];
__device__ float g_wk23[9*CIN*32*4];

__device__ __forceinline__ float hsig(float z) {
    return fminf(fmaxf(0.2f*z + 0.5f, 0.0f), 1.0f);
}

__device__ __forceinline__ void fma_x2(u64& acc, u64 s, u64 w) {
    asm("fma.rn.f32x2 %0, %1, %2, %3;" : "=l"(acc) : "l"(s), "l"(w), "l"(acc));
}
__device__ __forceinline__ u64 pack2(float s) {
    u64 r;
    asm("mov.b64 %0, {%1, %1};" : "=l"(r) : "f"(s));
    return r;
}
__device__ __forceinline__ float2 unpack2(u64 v) {
    float2 f;
    asm("mov.b64 {%0, %1}, %2;" : "=f"(f.x), "=f"(f.y) : "l"(v));
    return f;
}

// ---------------------------------------------------------------------------
// Weight transpose prep.
// ---------------------------------------------------------------------------
__global__ __launch_bounds__(128)
void prep_weights(const float* __restrict__ wk, const float* __restrict__ rw)
{
    const int i = blockIdx.x * 128 + threadIdx.x;
    if (i < 9*COUT*32) {
        const int j  = i & 31;
        const int ci = (i >> 5) & 63;
        const int k  = i >> 11;
        const float* s = rw + ((size_t)(k*COUT + ci))*GG + 2*j;
        ((float4*)g_rw01)[i] = make_float4(s[0],   s[1],   s[64],  s[65]);
        ((float4*)g_rw23)[i] = make_float4(s[128], s[129], s[192], s[193]);
    }
    const int m = i - 9*COUT*32;
    if (m >= 0 && m < 9*CIN*32) {
        const int j  = m & 31;
        const int ci = (m >> 5) & 31;
        const int k  = m >> 10;
        const float* s = wk + ((size_t)(k*CIN + ci))*GG + 2*j;
        ((float4*)g_wk01)[m] = make_float4(s[0],   s[1],   s[64],  s[65]);
        ((float4*)g_wk23)[m] = make_float4(s[128], s[129], s[192], s[193]);
    }
}

// Chunked smem weight tile: [9 taps][4 ci][32 lanes] float4, for each of 2 arrays.
#define CHUNK 4
#define TILE4 (9*CHUNK*32)    // 1152 float4 per array

// ---------------------------------------------------------------------------
// Phase 1: input-to-gate conv for ONE timestep t (512 blocks).
// Thread: 8 pixels x (2 channels x 4 gates). Block 128 thr.
// ---------------------------------------------------------------------------
__global__ __launch_bounds__(128, 4)
void input_conv_kernel(const float* __restrict__ x,
                       const float* __restrict__ bias,
                       const int t)
{
    __shared__ float4 s01[TILE4];
    __shared__ float4 s23[TILE4];

    const int tx   = threadIdx.x;
    const int lane = tx & 31;
    const int co0  = lane * 2;
    const int pg   = tx >> 5;
    const int bid  = blockIdx.x;
    const int b    = bid >> 7;                 // 0..3
    const int bt   = b*TT + t;
    const int r    = bid & 127;
    const int py   = r >> 1;
    const int px0  = (r & 1) * 32 + pg * 8;
    const bool okL = (px0 > 0);
    const bool okR = (px0 < WW - 8);

    u64 acc[4][8];
    #pragma unroll
    for (int g = 0; g < 4; g++) {
        u64 bv = *(const u64*)(bias + g*COUT + co0);
        #pragma unroll
        for (int p = 0; p < 8; p++) acc[g][p] = bv;
    }

    const int iy0 = py - 1;
    const float* __restrict__ xbase = x + ((size_t)(bt*HH))*WW*CIN;

    #pragma unroll 1
    for (int cc = 0; cc < CIN; cc += CHUNK) {
        __syncthreads();
        #pragma unroll
        for (int i = tx; i < TILE4; i += 128) {
            const int tap  = i >> 7;
            const int rest = i & 127;
            const size_t src = (size_t)(tap*CIN + cc)*32 + rest;
            s01[i] = ((const float4*)g_wk01)[src];
            s23[i] = ((const float4*)g_wk23)[src];
        }
        __syncthreads();

        #pragma unroll
        for (int ky = 0; ky < 3; ky++) {
            const int iy = iy0 + ky;
            if ((unsigned)iy >= HH) continue;
            const float* __restrict__ xrow = xbase + ((size_t)iy*WW)*CIN;
            #pragma unroll
            for (int c4 = 0; c4 < CHUNK; c4++) {
                const int ci = cc + c4;
                u64 hv2[10];
                hv2[0] = okL ? pack2(xrow[(size_t)(px0-1)*CIN + ci]) : 0ULL;
                #pragma unroll
                for (int j = 1; j < 9; j++)
                    hv2[j] = pack2(xrow[(size_t)(px0-1+j)*CIN + ci]);
                hv2[9] = okR ? pack2(xrow[(size_t)(px0+8)*CIN + ci]) : 0ULL;
                #pragma unroll
                for (int kx = 0; kx < 3; kx++) {
                    const int sidx = ((ky*3+kx)*CHUNK + c4)*32 + lane;
                    const ulonglong2 wA = *reinterpret_cast<const ulonglong2*>(&s01[sidx]);
                    const ulonglong2 wB = *reinterpret_cast<const ulonglong2*>(&s23[sidx]);
                    #pragma unroll
                    for (int p = 0; p < 8; p++) {
                        const u64 s2 = hv2[p + kx];
                        fma_x2(acc[0][p], s2, wA.x);
                        fma_x2(acc[1][p], s2, wA.y);
                        fma_x2(acc[2][p], s2, wB.x);
                        fma_x2(acc[3][p], s2, wB.y);
                    }
                }
            }
        }
    }

    const size_t rowbase = ((size_t)bt*HH + py)*WW;
    #pragma unroll
    for (int p = 0; p < 8; p++) {
        float* __restrict__ o = g_gx + (rowbase + px0 + p)*GG + co0;
        *(u64*)(o + 0*COUT) = acc[0][p];
        *(u64*)(o + 1*COUT) = acc[1][p];
        *(u64*)(o + 2*COUT) = acc[2][p];
        *(u64*)(o + 3*COUT) = acc[3][p];
    }
}

// ---------------------------------------------------------------------------
// Phase 2: one recurrent step with smem-staged weights (round-9 winner).
// Thread: 8 pixels x (2 channels x 4 gates) = 32 packed accumulators.
// Block: 128 thr = 4 warps x 32 lanes = 32 px. Grid: B*H*2 = 512.
// ---------------------------------------------------------------------------
template<bool FIRST>
__global__ __launch_bounds__(128, 4)
void step_kernel(float* __restrict__ y,
                 const int t,
                 const float* __restrict__ gamma,
                 const float* __restrict__ beta,
                 const float* __restrict__ mmean,
                 const float* __restrict__ mvar)
{
    __shared__ float4 s01[TILE4];
    __shared__ float4 s23[TILE4];

    const float* __restrict__ hprevd = (t & 1) ? g_h0d : g_h1d;
    float*       __restrict__ hnewd  = (t & 1) ? g_h1d : g_h0d;

    const int tx   = threadIdx.x;
    const int lane = tx & 31;
    const int co0  = lane * 2;
    const int pg   = tx >> 5;
    const int bid  = blockIdx.x;
    const int b    = bid >> 7;
    const int r    = bid & 127;
    const int py   = r >> 1;
    const int px0  = (r & 1) * 32 + pg * 8;
    const bool okL = (px0 > 0);
    const bool okR = (px0 < WW - 8);

    u64 acc[4][8];
    const size_t gxrow = ((size_t)(b*TT + t)*HH + py)*WW;
    #pragma unroll
    for (int p = 0; p < 8; p++) {
        const float* __restrict__ gp = g_gx + (gxrow + px0 + p)*GG + co0;
        acc[0][p] = *(const u64*)(gp + 0*COUT);
        acc[1][p] = *(const u64*)(gp + 1*COUT);
        acc[2][p] = *(const u64*)(gp + 2*COUT);
        acc[3][p] = *(const u64*)(gp + 3*COUT);
    }

    if (!FIRST) {
        const int iy0 = py - 1;
        const float* __restrict__ hbase = hprevd + ((size_t)(b*HH))*WW*(COUT*2);

        #pragma unroll 1
        for (int cc = 0; cc < COUT; cc += CHUNK) {
            __syncthreads();
            #pragma unroll
            for (int i = tx; i < TILE4; i += 128) {
                const int tap  = i >> 7;
                const int rest = i & 127;
                const size_t src = (size_t)(tap*COUT + cc)*32 + rest;
                s01[i] = ((const float4*)g_rw01)[src];
                s23[i] = ((const float4*)g_rw23)[src];
            }
            __syncthreads();

            #pragma unroll
            for (int ky = 0; ky < 3; ky++) {
                const int iy = iy0 + ky;
                if ((unsigned)iy >= HH) continue;
                const float* __restrict__ hrow = hbase + ((size_t)iy*WW)*(COUT*2);
                #pragma unroll
                for (int c4 = 0; c4 < CHUNK; c4++) {
                    const int ci = cc + c4;
                    u64 hv2[10];
                    hv2[0] = okL ? *(const u64*)(hrow + (size_t)(px0-1)*(COUT*2) + ci*2) : 0ULL;
                    #pragma unroll
                    for (int j = 1; j < 9; j++)
                        hv2[j] = *(const u64*)(hrow + (size_t)(px0-1+j)*(COUT*2) + ci*2);
                    hv2[9] = okR ? *(const u64*)(hrow + (size_t)(px0+8)*(COUT*2) + ci*2) : 0ULL;
                    #pragma unroll
                    for (int kx = 0; kx < 3; kx++) {
                        const int sidx = ((ky*3+kx)*CHUNK + c4)*32 + lane;
                        const ulonglong2 wA = *reinterpret_cast<const ulonglong2*>(&s01[sidx]);
                        const ulonglong2 wB = *reinterpret_cast<const ulonglong2*>(&s23[sidx]);
                        #pragma unroll
                        for (int p = 0; p < 8; p++) {
                            const u64 s2 = hv2[p + kx];
                            fma_x2(acc[0][p], s2, wA.x);
                            fma_x2(acc[1][p], s2, wA.y);
                            fma_x2(acc[2][p], s2, wB.x);
                            fma_x2(acc[3][p], s2, wB.y);
                        }
                    }
                }
            }
        }
    }

    // BN constants for this thread's 2 channels
    float2 gm  = *(const float2*)(gamma + co0);
    float2 bt2 = *(const float2*)(beta  + co0);
    float2 mm  = *(const float2*)(mmean + co0);
    float2 mv  = *(const float2*)(mvar  + co0);
    float2 inv, add;
    inv.x = gm.x * rsqrtf(mv.x + 1e-3f); add.x = bt2.x - mm.x*inv.x;
    inv.y = gm.y * rsqrtf(mv.y + 1e-3f); add.y = bt2.y - mm.y*inv.y;

    const size_t pixrow = ((size_t)b*HH + py)*WW;
    #pragma unroll
    for (int p = 0; p < 8; p++) {
        const size_t pix = pixrow + px0 + p;

        float2 gi = unpack2(acc[0][p]);
        float2 gf = unpack2(acc[1][p]);
        float2 gg = unpack2(acc[2][p]);
        float2 go = unpack2(acc[3][p]);

        float2 i2, f2, o2;
        i2.x = hsig(gi.x); i2.y = hsig(gi.y);
        f2.x = hsig(gf.x); f2.y = hsig(gf.y);
        o2.x = hsig(go.x); o2.y = hsig(go.y);

        float* __restrict__ cp = g_c + pix*COUT + co0;
        float2 cold = FIRST ? make_float2(0.f,0.f) : *(const float2*)cp;

        float2 cn;
        cn.x = f2.x*cold.x + i2.x*tanhf(gg.x);
        cn.y = f2.y*cold.y + i2.y*tanhf(gg.y);
        *(float2*)cp = cn;

        float2 h2;
        h2.x = o2.x * tanhf(cn.x);
        h2.y = o2.y * tanhf(cn.y);
        *(float4*)(hnewd + pix*(COUT*2) + co0*2) = make_float4(h2.x, h2.x, h2.y, h2.y);

        float2 yv;
        yv.x = h2.x*inv.x + add.x;
        yv.y = h2.y*inv.y + add.y;
        float* __restrict__ yp = y + (gxrow + px0 + p)*COUT + co0;
        *(float2*)yp = yv;
    }
}

extern "C" void kernel_launch(void* const* d_in, const int* in_sizes, int n_in,
                              void* d_out, int out_size)
{
    const float* x      = (const float*)d_in[0];
    const float* wk     = (const float*)d_in[1];
    const float* rw     = (const float*)d_in[2];
    const float* bias   = (const float*)d_in[3];
    const float* gamma  = (const float*)d_in[4];
    const float* beta   = (const float*)d_in[5];
    const float* mmean  = (const float*)d_in[6];
    const float* mvar   = (const float*)d_in[7];
    float* y = (float*)d_out;

    // Side stream + events for conv/step overlap (graph-capturable fork/join).
    cudaStream_t s2;
    cudaStreamCreateWithFlags(&s2, cudaStreamNonBlocking);
    cudaEvent_t evPrep;
    cudaEvent_t evConv[TT];
    cudaEventCreateWithFlags(&evPrep, cudaEventDisableTiming);
    for (int t = 0; t < TT; t++)
        cudaEventCreateWithFlags(&evConv[t], cudaEventDisableTiming);

    // Prep on main stream.
    const int n_prep = 9*COUT*32 + 9*CIN*32;
    prep_weights<<<(n_prep + 127)/128, 128>>>(wk, rw);
    cudaEventRecord(evPrep, 0);

    // Fork: per-timestep input convs on s2 (each 512 blocks).
    cudaStreamWaitEvent(s2, evPrep, 0);
    for (int t = 0; t < TT; t++) {
        input_conv_kernel<<<BB*HH*2, 128, 0, s2>>>(x, bias, t);
        cudaEventRecord(evConv[t], s2);
    }

    // Main stream: 16 sequential steps; step t joins on conv_t.
    const int nblk = BB*HH*2;
    cudaStreamWaitEvent(0, evConv[0], 0);
    step_kernel<true><<<nblk, 128>>>(y, 0, gamma, beta, mmean, mvar);
    for (int t = 1; t < TT; t++) {
        cudaStreamWaitEvent(0, evConv[t], 0);
        step_kernel<false><<<nblk, 128>>>(y, t, gamma, beta, mmean, mvar);
    }
    // Note: stream/events are intentionally not destroyed here — destruction
    // during an active capture is illegal; objects are host-side only.
}

// round 14
// speedup vs baseline: 2.0474x; 1.5425x over previous
#include <cuda_runtime.h>
#include <cuda_bf16.h>
#include <math.h>

#define BB 4
#define TT 16
#define HH 64
#define WW 64
#define CIN 32
#define COUT 64
#define GG 256

// Padded pixel space for implicit-GEMM conv
#define PW 66
#define PHW (PW*PW)            // 4356
#define PTOT (BB*PHW)          // 17424
#define NTILE 137              // ceil(17424/128)
#define PALLOC (NTILE*128)     // 17536
#define GUARD 128
#define HPX (PALLOC + 2*GUARD) // 17792

typedef unsigned long long u64;
typedef unsigned int u32;

// ---------------- device scratch (zero-initialized) -------------------------
__device__ float g_gx [(size_t)BB*TT*HH*WW*GG];       // input-conv gates (fp32)
__device__ float g_rec[(size_t)PALLOC*GG];            // recurrent-conv gates (fp32)
__device__ float g_c  [(size_t)BB*HH*WW*COUT];        // cell state
// Ping-pong hidden state, padded layout, bf16 hi/lo split. Pads stay 0.
__device__ __align__(16) __nv_bfloat16 g_h_hi0[(size_t)HPX*COUT];
__device__ __align__(16) __nv_bfloat16 g_h_lo0[(size_t)HPX*COUT];
__device__ __align__(16) __nv_bfloat16 g_h_hi1[(size_t)HPX*COUT];
__device__ __align__(16) __nv_bfloat16 g_h_lo1[(size_t)HPX*COUT];
// Recurrent weights as col-major B: [tap][n=256][k=64], bf16 hi/lo
__device__ __align__(16) __nv_bfloat16 g_Bhi[9*256*64];
__device__ __align__(16) __nv_bfloat16 g_Blo[9*256*64];
// Split transposed weights for scalar input conv
__device__ float g_wk01[9*CIN*32*4];
__device__ float g_wk23[9*CIN*32*4];

// ---------------- helpers ----------------------------------------------------
__device__ __forceinline__ float hsig(float z) {
    return fminf(fmaxf(0.2f*z + 0.5f, 0.0f), 1.0f);
}
__device__ __forceinline__ void fma_x2(u64& acc, u64 s, u64 w) {
    asm("fma.rn.f32x2 %0, %1, %2, %3;" : "=l"(acc) : "l"(s), "l"(w), "l"(acc));
}
__device__ __forceinline__ u64 pack2(float s) {
    u64 r; asm("mov.b64 %0, {%1, %1};" : "=l"(r) : "f"(s)); return r;
}
__device__ __forceinline__ u32 smem_to_u32(const void* p) {
    u32 a; asm("{ .reg .u64 t; cvta.to.shared.u64 t, %1; cvt.u32.u64 %0, t; }" : "=r"(a) : "l"(p));
    return a;
}

#define LDSM_X4(r0, r1, r2, r3, addr) \
    asm volatile("ldmatrix.sync.aligned.m8n8.x4.shared.b16 {%0,%1,%2,%3}, [%4];" \
        : "=r"(r0), "=r"(r1), "=r"(r2), "=r"(r3) : "r"(addr))

#define MMA_BF16(c, a, b) \
    asm volatile("mma.sync.aligned.m16n8k16.row.col.f32.bf16.bf16.f32 " \
        "{%0,%1,%2,%3}, {%4,%5,%6,%7}, {%8,%9}, {%0,%1,%2,%3};" \
        : "+f"((c)[0]), "+f"((c)[1]), "+f"((c)[2]), "+f"((c)[3]) \
        : "r"((a)[0]), "r"((a)[1]), "r"((a)[2]), "r"((a)[3]), \
          "r"((b)[0]), "r"((b)[1]))

// ---------------- prep kernels ------------------------------------------------
__global__ __launch_bounds__(128)
void prep_weights(const float* __restrict__ wk)
{
    const int m = blockIdx.x * 128 + threadIdx.x;
    if (m < 9*CIN*32) {
        const int j  = m & 31;
        const int ci = (m >> 5) & 31;
        const int k  = m >> 10;
        const float* s = wk + ((size_t)(k*CIN + ci))*GG + 2*j;
        ((float4*)g_wk01)[m] = make_float4(s[0],   s[1],   s[64],  s[65]);
        ((float4*)g_wk23)[m] = make_float4(s[128], s[129], s[192], s[193]);
    }
}

__global__ __launch_bounds__(256)
void prep_rw_bf16(const float* __restrict__ rw)
{
    const int i = blockIdx.x * 256 + threadIdx.x;
    if (i >= 9*256*64) return;
    const int k   = i & 63;
    const int n   = (i >> 6) & 255;
    const int tap = i >> 14;
    const float v = rw[((size_t)(tap*COUT + k))*GG + n];
    const __nv_bfloat16 h = __float2bfloat16(v);
    g_Bhi[i] = h;
    g_Blo[i] = __float2bfloat16(v - __bfloat162float(h));
}

// ---------------- scalar input conv (round-12 winner) -------------------------
#define CHUNK 4
#define TILE4 (9*CHUNK*32)

__global__ __launch_bounds__(128, 4)
void input_conv_kernel(const float* __restrict__ x,
                       const float* __restrict__ bias,
                       const int t0)
{
    __shared__ float4 s01[TILE4];
    __shared__ float4 s23[TILE4];

    const int tx   = threadIdx.x;
    const int lane = tx & 31;
    const int co0  = lane * 2;
    const int pg   = tx >> 5;
    const int bid  = blockIdx.x;
    const int t    = t0 + (bid >> 9);
    const int inner= bid & 511;
    const int b    = inner >> 7;
    const int bt   = b*TT + t;
    const int r    = inner & 127;
    const int py   = r >> 1;
    const int px0  = (r & 1) * 32 + pg * 8;
    const bool okL = (px0 > 0);
    const bool okR = (px0 < WW - 8);

    u64 acc[4][8];
    #pragma unroll
    for (int g = 0; g < 4; g++) {
        u64 bv = *(const u64*)(bias + g*COUT + co0);
        #pragma unroll
        for (int p = 0; p < 8; p++) acc[g][p] = bv;
    }

    const int iy0 = py - 1;
    const float* __restrict__ xbase = x + ((size_t)(bt*HH))*WW*CIN;

    #pragma unroll 1
    for (int cc = 0; cc < CIN; cc += CHUNK) {
        __syncthreads();
        #pragma unroll
        for (int i = tx; i < TILE4; i += 128) {
            const int tap  = i >> 7;
            const int rest = i & 127;
            const size_t src = (size_t)(tap*CIN + cc)*32 + rest;
            s01[i] = ((const float4*)g_wk01)[src];
            s23[i] = ((const float4*)g_wk23)[src];
        }
        __syncthreads();

        #pragma unroll
        for (int ky = 0; ky < 3; ky++) {
            const int iy = iy0 + ky;
            if ((unsigned)iy >= HH) continue;
            const float* __restrict__ xrow = xbase + ((size_t)iy*WW)*CIN;
            #pragma unroll
            for (int c4 = 0; c4 < CHUNK; c4++) {
                const int ci = cc + c4;
                u64 hv2[10];
                hv2[0] = okL ? pack2(xrow[(size_t)(px0-1)*CIN + ci]) : 0ULL;
                #pragma unroll
                for (int j = 1; j < 9; j++)
                    hv2[j] = pack2(xrow[(size_t)(px0-1+j)*CIN + ci]);
                hv2[9] = okR ? pack2(xrow[(size_t)(px0+8)*CIN + ci]) : 0ULL;
                #pragma unroll
                for (int kx = 0; kx < 3; kx++) {
                    const int sidx = ((ky*3+kx)*CHUNK + c4)*32 + lane;
                    const ulonglong2 wA = *reinterpret_cast<const ulonglong2*>(&s01[sidx]);
                    const ulonglong2 wB = *reinterpret_cast<const ulonglong2*>(&s23[sidx]);
                    #pragma unroll
                    for (int p = 0; p < 8; p++) {
                        const u64 s2 = hv2[p + kx];
                        fma_x2(acc[0][p], s2, wA.x);
                        fma_x2(acc[1][p], s2, wA.y);
                        fma_x2(acc[2][p], s2, wB.x);
                        fma_x2(acc[3][p], s2, wB.y);
                    }
                }
            }
        }
    }

    const size_t rowbase = ((size_t)bt*HH + py)*WW;
    #pragma unroll
    for (int p = 0; p < 8; p++) {
        float* __restrict__ o = g_gx + (rowbase + px0 + p)*GG + co0;
        *(u64*)(o + 0*COUT) = acc[0][p];
        *(u64*)(o + 1*COUT) = acc[1][p];
        *(u64*)(o + 2*COUT) = acc[2][p];
        *(u64*)(o + 3*COUT) = acc[3][p];
    }
}

// ---------------- HMMA recurrent GEMM -----------------------------------------
// smem: A window hi/lo (264 rows x 128B) + B tile hi/lo (256 rows x 128B).
#define SM_A_HI 0
#define SM_A_LO 33792
#define SM_B_HI 67584
#define SM_B_LO 100352
#define GEMM_SMEM 133120

__device__ __forceinline__ u32 swz(u32 row, u32 chunk) {
    return row*128u + ((chunk ^ (row & 7u)) << 4);
}

__global__ __launch_bounds__(512, 1)
void step_gemm(const int t)
{
    extern __shared__ char smem[];
    const u32 sbase = smem_to_u32(smem);
    const int tid  = threadIdx.x;
    const int wid  = tid >> 5;
    const int lane = tid & 31;
    const int tile = blockIdx.x;
    const int m_base = tile * 128;

    const __nv_bfloat16* __restrict__ ph_hi = (t & 1) ? g_h_hi0 : g_h_hi1;
    const __nv_bfloat16* __restrict__ ph_lo = (t & 1) ? g_h_lo0 : g_h_lo1;

    // Fill A window: padded-h rows [m_base-67, m_base+197) (264 rows)
    {
        const size_t src0 = (size_t)(GUARD + m_base - 67) * COUT;
        for (int i = tid; i < 264*8; i += 512) {
            const int row = i >> 3, c = i & 7;
            const u32 d = swz((u32)row, (u32)c);
            *(uint4*)(smem + SM_A_HI + d) =
                *(const uint4*)(ph_hi + src0 + (size_t)row*COUT + c*8);
            *(uint4*)(smem + SM_A_LO + d) =
                *(const uint4*)(ph_lo + src0 + (size_t)row*COUT + c*8);
        }
    }

    const int wm = wid >> 3;            // 0..1  (m64 tile)
    const int wn = wid & 7;             // 0..7  (n32 tile)
    const int n0 = wn * 32;

    const int lmat = lane >> 3;
    const int lrow = lane & 7;
    // A ldmatrix.x4: mat0 rows+0 chunk+0, mat1 rows+8 chunk+0, mat2 rows+0 +1, mat3 rows+8 +1
    const int aRowLane  = wm*64 + 67 + (lmat & 1)*8 + lrow;   // + aoff[tap] + ms*16
    const int aChunkSel = lmat >> 1;
    // B ldmatrix.x4 (#q): mat0 b0[2q], mat1 b1[2q], mat2 b0[2q+1], mat3 b1[2q+1]
    const int bRowLane  = n0 + (lmat >> 1)*8 + lrow;          // + q*16
    const int bChunkSel = lmat & 1;

    float acc[4][4][4];
    #pragma unroll
    for (int ms = 0; ms < 4; ms++)
        #pragma unroll
        for (int nf = 0; nf < 4; nf++)
            #pragma unroll
            for (int e = 0; e < 4; e++) acc[ms][nf][e] = 0.0f;

    const int aoff[9] = {-PW-1, -PW, -PW+1, -1, 0, 1, PW-1, PW, PW+1};

    __syncthreads();   // A window ready

    #pragma unroll 1
    for (int tap = 0; tap < 9; tap++) {
        if (tap) __syncthreads();      // prior tap's B consumption done
        // Fill B tile for this tap (256 rows x 8 chunks, hi+lo)
        for (int i = tid; i < 256*8; i += 512) {
            const int row = i >> 3, c = i & 7;
            const u32 d = swz((u32)row, (u32)c);
            const size_t src = (size_t)tap*16384 + (size_t)row*64 + c*8;
            *(uint4*)(smem + SM_B_HI + d) = *(const uint4*)(g_Bhi + src);
            *(uint4*)(smem + SM_B_LO + d) = *(const uint4*)(g_Blo + src);
        }
        __syncthreads();

        #pragma unroll
        for (int kc = 0; kc < 4; kc++) {
            // A hi fragments (m64 = 4 x m16)
            u32 ah[4][4];
            #pragma unroll
            for (int ms = 0; ms < 4; ms++) {
                const int wrow = aRowLane + ms*16 + aoff[tap];
                const u32 addr = sbase + SM_A_HI + swz((u32)wrow, (u32)(2*kc + aChunkSel));
                LDSM_X4(ah[ms][0], ah[ms][1], ah[ms][2], ah[ms][3], addr);
            }
            // B hi fragments (n32 = 4 x n8)
            u32 bb[4][2];
            #pragma unroll
            for (int q = 0; q < 2; q++) {
                const u32 addr = sbase + SM_B_HI +
                    swz((u32)(bRowLane + q*16), (u32)(2*kc + bChunkSel));
                LDSM_X4(bb[2*q][0], bb[2*q][1], bb[2*q+1][0], bb[2*q+1][1], addr);
            }
            #pragma unroll
            for (int ms = 0; ms < 4; ms++)
                #pragma unroll
                for (int nf = 0; nf < 4; nf++)
                    MMA_BF16(acc[ms][nf], ah[ms], bb[nf]);

            // B lo pass (Ahi * Blo)
            #pragma unroll
            for (int q = 0; q < 2; q++) {
                const u32 addr = sbase + SM_B_LO +
                    swz((u32)(bRowLane + q*16), (u32)(2*kc + bChunkSel));
                LDSM_X4(bb[2*q][0], bb[2*q][1], bb[2*q+1][0], bb[2*q+1][1], addr);
            }
            #pragma unroll
            for (int ms = 0; ms < 4; ms++)
                #pragma unroll
                for (int nf = 0; nf < 4; nf++)
                    MMA_BF16(acc[ms][nf], ah[ms], bb[nf]);

            // A lo pass (Alo * Bhi): reload Bhi, overwrite ah with Alo
            #pragma unroll
            for (int ms = 0; ms < 4; ms++) {
                const int wrow = aRowLane + ms*16 + aoff[tap];
                const u32 addr = sbase + SM_A_LO + swz((u32)wrow, (u32)(2*kc + aChunkSel));
                LDSM_X4(ah[ms][0], ah[ms][1], ah[ms][2], ah[ms][3], addr);
            }
            #pragma unroll
            for (int q = 0; q < 2; q++) {
                const u32 addr = sbase + SM_B_HI +
                    swz((u32)(bRowLane + q*16), (u32)(2*kc + bChunkSel));
                LDSM_X4(bb[2*q][0], bb[2*q][1], bb[2*q+1][0], bb[2*q+1][1], addr);
            }
            #pragma unroll
            for (int ms = 0; ms < 4; ms++)
                #pragma unroll
                for (int nf = 0; nf < 4; nf++)
                    MMA_BF16(acc[ms][nf], ah[ms], bb[nf]);
        }
    }

    // Store accumulators to g_rec (fp32)
    const int rbase = m_base + wm*64 + (lane >> 2);
    const int cbase = n0 + (lane & 3)*2;
    #pragma unroll
    for (int ms = 0; ms < 4; ms++) {
        #pragma unroll
        for (int nf = 0; nf < 4; nf++) {
            float* p0 = g_rec + (size_t)(rbase + ms*16    )*GG + cbase + nf*8;
            float* p1 = g_rec + (size_t)(rbase + ms*16 + 8)*GG + cbase + nf*8;
            *(float2*)p0 = make_float2(acc[ms][nf][0], acc[ms][nf][1]);
            *(float2*)p1 = make_float2(acc[ms][nf][2], acc[ms][nf][3]);
        }
    }
}

// ---------------- LSTM epilogue -----------------------------------------------
template<bool FIRST>
__global__ __launch_bounds__(256)
void step_epi(float* __restrict__ y, const int t,
              const float* __restrict__ gamma, const float* __restrict__ beta,
              const float* __restrict__ mmean, const float* __restrict__ mvar)
{
    const int gid = blockIdx.x * 256 + threadIdx.x;
    const int px  = gid >> 6;
    const int ch  = gid & 63;
    const int b   = px >> 12;
    const int rem = px & 4095;
    const int yy  = rem >> 6, xx = rem & 63;
    const int pad = b*PHW + (yy + 1)*PW + (xx + 1);

    const size_t gxb = ((size_t)(b*TT + t)*4096 + rem)*GG + ch;
    float gi = g_gx[gxb + 0*COUT];
    float gf = g_gx[gxb + 1*COUT];
    float gg = g_gx[gxb + 2*COUT];
    float go = g_gx[gxb + 3*COUT];
    if (!FIRST) {
        const size_t rb = (size_t)pad*GG + ch;
        gi += g_rec[rb + 0*COUT];
        gf += g_rec[rb + 1*COUT];
        gg += g_rec[rb + 2*COUT];
        go += g_rec[rb + 3*COUT];
    }
    const float iv = hsig(gi), fv = hsig(gf), ov = hsig(go);
    const size_t cb = (size_t)px*COUT + ch;
    const float cold = FIRST ? 0.0f : g_c[cb];
    const float cn = fv*cold + iv*tanhf(gg);
    g_c[cb] = cn;
    const float hval = ov * tanhf(cn);

    __nv_bfloat16* nh_hi = (t & 1) ? g_h_hi1 : g_h_hi0;
    __nv_bfloat16* nh_lo = (t & 1) ? g_h_lo1 : g_h_lo0;
    const __nv_bfloat16 hh = __float2bfloat16(hval);
    nh_hi[(size_t)(GUARD + pad)*COUT + ch] = hh;
    nh_lo[(size_t)(GUARD + pad)*COUT + ch] = __float2bfloat16(hval - __bfloat162float(hh));

    const float inv = gamma[ch] * rsqrtf(mvar[ch] + 1e-3f);
    y[((size_t)(b*TT + t)*4096 + rem)*COUT + ch] = hval*inv + (beta[ch] - mmean[ch]*inv);
}

// ---------------- host ----------------------------------------------------------
extern "C" void kernel_launch(void* const* d_in, const int* in_sizes, int n_in,
                              void* d_out, int out_size)
{
    const float* x      = (const float*)d_in[0];
    const float* wk     = (const float*)d_in[1];
    const float* rw     = (const float*)d_in[2];
    const float* bias   = (const float*)d_in[3];
    const float* gamma  = (const float*)d_in[4];
    const float* beta   = (const float*)d_in[5];
    const float* mmean  = (const float*)d_in[6];
    const float* mvar   = (const float*)d_in[7];
    float* y = (float*)d_out;

    cudaFuncSetAttribute(step_gemm, cudaFuncAttributeMaxDynamicSharedMemorySize, GEMM_SMEM);

    cudaStream_t s2;
    cudaStreamCreateWithFlags(&s2, cudaStreamNonBlocking);
    cudaEvent_t evPrep;
    cudaEvent_t evConv[4];
    cudaEventCreateWithFlags(&evPrep, cudaEventDisableTiming);
    for (int c = 0; c < 4; c++)
        cudaEventCreateWithFlags(&evConv[c], cudaEventDisableTiming);

    // Prep on main stream.
    prep_weights<<<(9*CIN*32 + 127)/128, 128>>>(wk);
    prep_rw_bf16<<<(9*256*64)/256, 256>>>(rw);
    cudaEventRecord(evPrep, 0);

    // Fork: input convs in 4 chunks of 4 timesteps on s2.
    cudaStreamWaitEvent(s2, evPrep, 0);
    for (int c = 0; c < 4; c++) {
        input_conv_kernel<<<4*512, 128, 0, s2>>>(x, bias, c*4);
        cudaEventRecord(evConv[c], s2);
    }

    // Main stream recurrence.
    const int epiBlocks = (BB*HH*WW*COUT)/256;   // 4096
    cudaStreamWaitEvent(0, evConv[0], 0);
    step_epi<true><<<epiBlocks, 256>>>(y, 0, gamma, beta, mmean, mvar);
    for (int t = 1; t < TT; t++) {
        step_gemm<<<NTILE, 512, GEMM_SMEM>>>(t);
        if ((t & 3) == 0) cudaStreamWaitEvent(0, evConv[t >> 2], 0);
        step_epi<false><<<epiBlocks, 256>>>(y, t, gamma, beta, mmean, mvar);
    }
}